// round 4
// baseline (speedup 1.0000x reference)
#include <cuda_runtime.h>
#include <cuda_bf16.h>

#define H     2048
#define G4    8192          // 4*H gate rows
#define V     28
#define T     512
#define NCTA  148
#define CPB   14            // h-indices per CTA (148*14 >= 2048)
#define WMAT  16777216      // G4*H elements per matrix

// ---- device scratch (no allocations allowed) ----
__device__ float    g_table[2u * V * G4];   // [enc/dec][vocab][4H] gate table, biases folded
__device__ short    g_Wq[2][WMAT];          // int16-quantized Whh (enc, dec)
__device__ float    g_wscale[2][G4];        // per-row dequant scales
__device__ float    g_h[2][H];              // double-buffered hidden state
__device__ unsigned g_bar_count = 0;
__device__ unsigned g_bar_phase = 0;

__device__ __forceinline__ float warpsum(float v) {
#pragma unroll
    for (int o = 16; o; o >>= 1) v += __shfl_xor_sync(0xffffffffu, v, o);
    return v;
}
__device__ __forceinline__ float sigm(float x) { return 1.0f / (1.0f + expf(-x)); }

// Software grid barrier: all NCTA CTAs are co-resident (grid <= #SMs, 1 CTA/SM).
__device__ __forceinline__ void grid_sync() {
    __syncthreads();
    if (threadIdx.x == 0) {
        volatile unsigned* ph = &g_bar_phase;
        unsigned p = *ph;
        __threadfence();
        unsigned arr = atomicAdd(&g_bar_count, 1u);
        if (arr == NCTA - 1u) {
            g_bar_count = 0u;
            __threadfence();
            atomicAdd(&g_bar_phase, 1u);
        } else {
            while (*ph == p) { }
            __threadfence();
        }
    }
    __syncthreads();
}

// ---------------------------------------------------------------------------
// Quantize Whh rows to int16 with per-row fp32 scale.
// One block per gate row (16384 blocks x 256 threads). Row kept in registers.
// ---------------------------------------------------------------------------
__global__ __launch_bounds__(256) void k_quant(
    const float* __restrict__ encW, const float* __restrict__ decW)
{
    __shared__ float s_max[8];
    const int r     = blockIdx.x;       // 0..16383
    const int which = r >> 13;
    const int row   = r & (G4 - 1);
    const int tid = threadIdx.x, lane = tid & 31, w = tid >> 5;

    const float4* W4 = reinterpret_cast<const float4*>(
        (which ? decW : encW) + (size_t)row * H);

    float4 v0 = __ldg(&W4[tid]);
    float4 v1 = __ldg(&W4[tid + 256]);

    float m = fmaxf(fmaxf(fabsf(v0.x), fabsf(v0.y)), fmaxf(fabsf(v0.z), fabsf(v0.w)));
    m = fmaxf(m, fmaxf(fmaxf(fabsf(v1.x), fabsf(v1.y)), fmaxf(fabsf(v1.z), fabsf(v1.w))));
#pragma unroll
    for (int o = 16; o; o >>= 1) m = fmaxf(m, __shfl_xor_sync(0xffffffffu, m, o));
    if (lane == 0) s_max[w] = m;
    __syncthreads();
    if (tid == 0) {
        float mm = s_max[0];
#pragma unroll
        for (int i = 1; i < 8; i++) mm = fmaxf(mm, s_max[i]);
        s_max[0] = mm;
        g_wscale[which][row] = mm * (1.0f / 32766.0f);
    }
    __syncthreads();
    const float mv  = s_max[0];
    const float inv = (mv > 0.0f) ? (32766.0f / mv) : 0.0f;

    short4* Q4 = reinterpret_cast<short4*>(&g_Wq[which][(size_t)row * H]);
    short4 q;
    q.x = (short)__float2int_rn(v0.x * inv);
    q.y = (short)__float2int_rn(v0.y * inv);
    q.z = (short)__float2int_rn(v0.z * inv);
    q.w = (short)__float2int_rn(v0.w * inv);
    Q4[tid] = q;
    q.x = (short)__float2int_rn(v1.x * inv);
    q.y = (short)__float2int_rn(v1.y * inv);
    q.z = (short)__float2int_rn(v1.z * inv);
    q.w = (short)__float2int_rn(v1.w * inv);
    Q4[tid + 256] = q;
}

// ---------------------------------------------------------------------------
// Precompute per-vocab gate tables:
//   table[which][v][row] = dot(Wih[row], emb[v]) + bih[row] + bhh[row]
// grid: 2048 blocks x 256 threads; 1 warp per gate row, emb tiled in smem.
// Block 0 also zeroes g_h[0] (initial hidden state).
// ---------------------------------------------------------------------------
__global__ __launch_bounds__(256) void k_pre(
    const float* __restrict__ enc_emb, const float* __restrict__ enc_Wih,
    const float* __restrict__ enc_bih, const float* __restrict__ enc_bhh,
    const float* __restrict__ dec_emb, const float* __restrict__ dec_Wih,
    const float* __restrict__ dec_bih, const float* __restrict__ dec_bhh)
{
    __shared__ __align__(16) float s_emb[V][256];
    const int tid = threadIdx.x, lane = tid & 31, warp = tid >> 5;

    if (blockIdx.x == 0) {
        for (int j = tid; j < H; j += 256) g_h[0][j] = 0.0f;
    }

    const int   which = (blockIdx.x >= 1024) ? 1 : 0;
    const float* emb = which ? dec_emb : enc_emb;
    const float* Wih = which ? dec_Wih : enc_Wih;
    const float* bih = which ? dec_bih : enc_bih;
    const float* bhh = which ? dec_bhh : enc_bhh;
    const int row = (blockIdx.x & 1023) * 8 + warp;   // 0..8191

    float acc[V];
#pragma unroll
    for (int v = 0; v < V; v++) acc[v] = 0.0f;

    for (int kt = 0; kt < 8; kt++) {
        const int k0 = kt * 256;
        __syncthreads();
        for (int idx = tid; idx < V * 256; idx += 256) {
            int v = idx >> 8, kk = idx & 255;
            s_emb[v][kk] = __ldg(&emb[v * H + k0 + kk]);
        }
        __syncthreads();
        const float4* Wr = reinterpret_cast<const float4*>(Wih + (size_t)row * H + k0);
#pragma unroll
        for (int it = 0; it < 2; it++) {
            const int kl = it * 32 + lane;            // float4 index within tile
            float4 w4 = __ldg(&Wr[kl]);
#pragma unroll
            for (int v = 0; v < V; v++) {
                float4 e = reinterpret_cast<const float4*>(s_emb[v])[kl];
                acc[v] += w4.x * e.x + w4.y * e.y + w4.z * e.z + w4.w * e.w;
            }
        }
    }

    float bias = 0.0f;
#pragma unroll
    for (int v = 0; v < V; v++) {
        float s = warpsum(acc[v]);
        if (lane == 0) {
            if (v == 0) bias = __ldg(&bih[row]) + __ldg(&bhh[row]);
            g_table[(size_t)which * V * G4 + (size_t)v * G4 + row] = s + bias;
        }
    }
}

// ---------------------------------------------------------------------------
// Persistent LSTM kernel: 148 CTAs x 1024 threads, grid barrier per step.
// Recurrent matvec now reads int16 weights (half the L2 traffic of fp32) and
// dequantizes with a per-row scale after the warp reduction; accumulation,
// h/c state, gate table and heads all stay fp32.
// ---------------------------------------------------------------------------
__global__ __launch_bounds__(1024, 1) void k_main(
    const int*   __restrict__ x,      const int*   __restrict__ target,
    const float* __restrict__ eps,
    const float* __restrict__ mu_W,    const float* __restrict__ mu_b,
    const float* __restrict__ lv_W,    const float* __restrict__ lv_b,
    float* __restrict__ out)
{
    __shared__ __align__(16) float s_h[H];
    __shared__ float s_gates[64];
    __shared__ float s_c[CPB];

    const int tid = threadIdx.x, lane = tid & 31, w = tid >> 5;
    const int j0 = blockIdx.x * CPB;
    int nloc = H - j0;
    if (nloc > CPB) nloc = CPB;
    if (nloc < 0)  nloc = 0;
    const int nrows = nloc * 4;

    if (tid < CPB) s_c[tid] = 0.0f;

    int rb = 0;  // read-buffer parity for g_h

    for (int phase = 0; phase < 2; phase++) {
        const short* Wq    = g_Wq[phase];
        const float* wsc   = g_wscale[phase];
        const float* table = g_table + (size_t)phase * V * G4;

        for (int t = 0; t < T; t++) {
            // broadcast full h into smem (L2-coherent loads)
            for (int j = tid; j < H; j += 1024) s_h[j] = __ldcg(&g_h[rb][j]);
            __syncthreads();

            const int tok = (phase == 0) ? __ldg(&x[t])
                                         : (t == 0 ? 0 : __ldg(&target[t - 1]));
            const float4* sh4 = reinterpret_cast<const float4*>(s_h);

            for (int fr = w; fr < nrows; fr += 32) {
                const int l = fr >> 2, gate = fr & 3;
                const int row = gate * H + j0 + l;
                const int4* W4 = reinterpret_cast<const int4*>(Wq + (size_t)row * H);
                float s = 0.0f;
#pragma unroll 4
                for (int i = lane; i < H / 8; i += 32) {   // int4 = 8 shorts
                    int4 a = __ldg(&W4[i]);
                    float4 h0 = sh4[2 * i];
                    float4 h1 = sh4[2 * i + 1];
                    short2 p;
                    p = *reinterpret_cast<short2*>(&a.x);
                    s += (float)p.x * h0.x + (float)p.y * h0.y;
                    p = *reinterpret_cast<short2*>(&a.y);
                    s += (float)p.x * h0.z + (float)p.y * h0.w;
                    p = *reinterpret_cast<short2*>(&a.z);
                    s += (float)p.x * h1.x + (float)p.y * h1.y;
                    p = *reinterpret_cast<short2*>(&a.w);
                    s += (float)p.x * h1.z + (float)p.y * h1.w;
                }
                s = warpsum(s);
                if (lane == 0)
                    s_gates[fr] = s * __ldg(&wsc[row]) +
                                  __ldg(&table[(size_t)tok * G4 + row]);
            }
            __syncthreads();

            if (tid < nloc) {
                const float gi = s_gates[tid * 4 + 0];
                const float gf = s_gates[tid * 4 + 1];
                const float gg = s_gates[tid * 4 + 2];
                const float go = s_gates[tid * 4 + 3];
                float c = sigm(gf) * s_c[tid] + sigm(gi) * tanhf(gg);
                s_c[tid] = c;
                float h = sigm(go) * tanhf(c);
                __stcg(&g_h[rb ^ 1][j0 + tid], h);
                if (phase)  // dec_outs
                    out[512 + (size_t)t * H + j0 + tid] = h;
            }
            __threadfence();
            grid_sync();
            rb ^= 1;
        }

        if (phase == 0) {
            // VAE heads: mu, logvar from h_enc (in g_h[rb]); z -> g_h[rb^1]
            for (int j = tid; j < H; j += 1024) s_h[j] = __ldcg(&g_h[rb][j]);
            __syncthreads();
            const float4* sh4 = reinterpret_cast<const float4*>(s_h);
            if (w < nloc * 2) {
                const int l = w >> 1, m = w & 1;
                const float* Wm = m ? lv_W : mu_W;
                const int row = j0 + l;
                const float4* W4 = reinterpret_cast<const float4*>(Wm) + (size_t)row * (H / 4);
                float s = 0.0f;
#pragma unroll 8
                for (int i = lane; i < H / 4; i += 32) {
                    float4 a = __ldg(&W4[i]);
                    float4 b = sh4[i];
                    s += a.x * b.x + a.y * b.y + a.z * b.z + a.w * b.w;
                }
                s = warpsum(s);
                if (lane == 0)
                    s_gates[w] = s + __ldg(&(m ? lv_b : mu_b)[row]);
            }
            __syncthreads();
            if (tid < nloc) {
                const int j = j0 + tid;
                const float mu = s_gates[tid * 2 + 0];
                const float lv = s_gates[tid * 2 + 1];
                out[512 + (size_t)T * H + j]     = mu;
                out[512 + (size_t)T * H + H + j] = lv;
                float z = mu + __ldg(&eps[j]) * expf(0.5f * lv);
                __stcg(&g_h[rb ^ 1][j], z);
            }
            __threadfence();
            grid_sync();
            rb ^= 1;
        }
    }
}

// ---------------------------------------------------------------------------
// Argmax over hidden dim of each decoder output row (first-index tie-break).
// ---------------------------------------------------------------------------
__global__ __launch_bounds__(256) void k_argmax(float* __restrict__ out)
{
    __shared__ float sv[256];
    __shared__ int   si[256];
    const int t = blockIdx.x;
    const float* row = out + 512 + (size_t)t * H;
    float best = -3.402823466e+38f;
    int   bi = 0;
    for (int j = threadIdx.x; j < H; j += 256) {
        float v = row[j];
        if (v > best) { best = v; bi = j; }
    }
    sv[threadIdx.x] = best;
    si[threadIdx.x] = bi;
    __syncthreads();
    for (int s = 128; s; s >>= 1) {
        if (threadIdx.x < s) {
            float ov = sv[threadIdx.x + s];
            int   oi = si[threadIdx.x + s];
            if (ov > sv[threadIdx.x] ||
                (ov == sv[threadIdx.x] && oi < si[threadIdx.x])) {
                sv[threadIdx.x] = ov;
                si[threadIdx.x] = oi;
            }
        }
        __syncthreads();
    }
    if (threadIdx.x == 0) out[t] = (float)si[0];
}

// ---------------------------------------------------------------------------
extern "C" void kernel_launch(void* const* d_in, const int* in_sizes, int n_in,
                              void* d_out, int out_size)
{
    const int*   x       = (const int*)  d_in[0];
    const int*   target  = (const int*)  d_in[1];
    const float* eps     = (const float*)d_in[2];
    const float* enc_emb = (const float*)d_in[3];
    const float* enc_Wih = (const float*)d_in[4];
    const float* enc_Whh = (const float*)d_in[5];
    const float* enc_bih = (const float*)d_in[6];
    const float* enc_bhh = (const float*)d_in[7];
    const float* mu_W    = (const float*)d_in[8];
    const float* mu_b    = (const float*)d_in[9];
    const float* lv_W    = (const float*)d_in[10];
    const float* lv_b    = (const float*)d_in[11];
    const float* dec_emb = (const float*)d_in[12];
    const float* dec_Wih = (const float*)d_in[13];
    const float* dec_Whh = (const float*)d_in[14];
    const float* dec_bih = (const float*)d_in[15];
    const float* dec_bhh = (const float*)d_in[16];
    float* out = (float*)d_out;

    k_pre<<<2048, 256>>>(enc_emb, enc_Wih, enc_bih, enc_bhh,
                         dec_emb, dec_Wih, dec_bih, dec_bhh);
    k_quant<<<2 * G4, 256>>>(enc_Whh, dec_Whh);
    k_main<<<NCTA, 1024>>>(x, target, eps,
                           mu_W, mu_b, lv_W, lv_b, out);
    k_argmax<<<512, 256>>>(out);
}

// round 5
// speedup vs baseline: 1.1208x; 1.1208x over previous
#include <cuda_runtime.h>
#include <cuda_bf16.h>

#define H     2048
#define G4    8192          // 4*H gate rows
#define V     28
#define T     512
#define NCTA  148
#define CPB   14            // h-indices per CTA (148*14 >= 2048)
#define ROWS  56            // gate rows per CTA
#define SMEM_ROWS 49        // rows resident in SMEM; rest (7) stream from L2
#define WMAT  16777216      // G4*H elements per matrix

// dynamic smem layout (u32 units)
#define OFF_W     0
#define OFF_H     (SMEM_ROWS * 1024)            // 50176
#define OFF_PART  (OFF_H + 2048)                // 52224  : 56 rows x 4 slices
#define OFF_GATES (OFF_PART + ROWS * 4)         // 52448
#define OFF_C     (OFF_GATES + ROWS)            // 52504
#define SMEM_U32  (OFF_C + CPB)                 // 52518
#define SMEM_BYTES (SMEM_U32 * 4)               // 210072

// ---- device scratch (no allocations allowed) ----
__device__ float    g_table[2u * V * G4];   // [enc/dec][vocab][4H] gate table, biases folded
__device__ short    g_Wq[2][WMAT];          // int16-quantized Whh (enc, dec)
__device__ float    g_wscale[2][G4];        // per-row dequant scales
__device__ float    g_h[2][H];              // double-buffered hidden state
__device__ unsigned g_bar_count = 0;
__device__ unsigned g_bar_phase = 0;

__device__ __forceinline__ float warpsum(float v) {
#pragma unroll
    for (int o = 16; o; o >>= 1) v += __shfl_xor_sync(0xffffffffu, v, o);
    return v;
}
__device__ __forceinline__ float sigm(float x) { return 1.0f / (1.0f + expf(-x)); }

// Software grid barrier: all NCTA CTAs are co-resident (grid <= #SMs, 1 CTA/SM).
__device__ __forceinline__ void grid_sync() {
    __syncthreads();
    if (threadIdx.x == 0) {
        volatile unsigned* ph = &g_bar_phase;
        unsigned p = *ph;
        __threadfence();
        unsigned arr = atomicAdd(&g_bar_count, 1u);
        if (arr == NCTA - 1u) {
            g_bar_count = 0u;
            __threadfence();
            atomicAdd(&g_bar_phase, 1u);
        } else {
            while (*ph == p) { }
            __threadfence();
        }
    }
    __syncthreads();
}

// ---------------------------------------------------------------------------
// Quantize Whh rows to int16 with per-row fp32 scale.
// ---------------------------------------------------------------------------
__global__ __launch_bounds__(256) void k_quant(
    const float* __restrict__ encW, const float* __restrict__ decW)
{
    __shared__ float s_max[8];
    const int r     = blockIdx.x;       // 0..16383
    const int which = r >> 13;
    const int row   = r & (G4 - 1);
    const int tid = threadIdx.x, lane = tid & 31, w = tid >> 5;

    const float4* W4 = reinterpret_cast<const float4*>(
        (which ? decW : encW) + (size_t)row * H);

    float4 v0 = __ldg(&W4[tid]);
    float4 v1 = __ldg(&W4[tid + 256]);

    float m = fmaxf(fmaxf(fabsf(v0.x), fabsf(v0.y)), fmaxf(fabsf(v0.z), fabsf(v0.w)));
    m = fmaxf(m, fmaxf(fmaxf(fabsf(v1.x), fabsf(v1.y)), fmaxf(fabsf(v1.z), fabsf(v1.w))));
#pragma unroll
    for (int o = 16; o; o >>= 1) m = fmaxf(m, __shfl_xor_sync(0xffffffffu, m, o));
    if (lane == 0) s_max[w] = m;
    __syncthreads();
    if (tid == 0) {
        float mm = s_max[0];
#pragma unroll
        for (int i = 1; i < 8; i++) mm = fmaxf(mm, s_max[i]);
        s_max[0] = mm;
        g_wscale[which][row] = mm * (1.0f / 32766.0f);
    }
    __syncthreads();
    const float mv  = s_max[0];
    const float inv = (mv > 0.0f) ? (32766.0f / mv) : 0.0f;

    short4* Q4 = reinterpret_cast<short4*>(&g_Wq[which][(size_t)row * H]);
    short4 q;
    q.x = (short)__float2int_rn(v0.x * inv);
    q.y = (short)__float2int_rn(v0.y * inv);
    q.z = (short)__float2int_rn(v0.z * inv);
    q.w = (short)__float2int_rn(v0.w * inv);
    Q4[tid] = q;
    q.x = (short)__float2int_rn(v1.x * inv);
    q.y = (short)__float2int_rn(v1.y * inv);
    q.z = (short)__float2int_rn(v1.z * inv);
    q.w = (short)__float2int_rn(v1.w * inv);
    Q4[tid + 256] = q;
}

// ---------------------------------------------------------------------------
// Precompute per-vocab gate tables (unchanged from round 3).
// ---------------------------------------------------------------------------
__global__ __launch_bounds__(256) void k_pre(
    const float* __restrict__ enc_emb, const float* __restrict__ enc_Wih,
    const float* __restrict__ enc_bih, const float* __restrict__ enc_bhh,
    const float* __restrict__ dec_emb, const float* __restrict__ dec_Wih,
    const float* __restrict__ dec_bih, const float* __restrict__ dec_bhh)
{
    __shared__ __align__(16) float s_emb[V][256];
    const int tid = threadIdx.x, lane = tid & 31, warp = tid >> 5;

    if (blockIdx.x == 0) {
        for (int j = tid; j < H; j += 256) g_h[0][j] = 0.0f;
    }

    const int   which = (blockIdx.x >= 1024) ? 1 : 0;
    const float* emb = which ? dec_emb : enc_emb;
    const float* Wih = which ? dec_Wih : enc_Wih;
    const float* bih = which ? dec_bih : enc_bih;
    const float* bhh = which ? dec_bhh : enc_bhh;
    const int row = (blockIdx.x & 1023) * 8 + warp;   // 0..8191

    float acc[V];
#pragma unroll
    for (int v = 0; v < V; v++) acc[v] = 0.0f;

    for (int kt = 0; kt < 8; kt++) {
        const int k0 = kt * 256;
        __syncthreads();
        for (int idx = tid; idx < V * 256; idx += 256) {
            int v = idx >> 8, kk = idx & 255;
            s_emb[v][kk] = __ldg(&emb[v * H + k0 + kk]);
        }
        __syncthreads();
        const float4* Wr = reinterpret_cast<const float4*>(Wih + (size_t)row * H + k0);
#pragma unroll
        for (int it = 0; it < 2; it++) {
            const int kl = it * 32 + lane;            // float4 index within tile
            float4 w4 = __ldg(&Wr[kl]);
#pragma unroll
            for (int v = 0; v < V; v++) {
                float4 e = reinterpret_cast<const float4*>(s_emb[v])[kl];
                acc[v] += w4.x * e.x + w4.y * e.y + w4.z * e.z + w4.w * e.w;
            }
        }
    }

    float bias = 0.0f;
#pragma unroll
    for (int v = 0; v < V; v++) {
        float s = warpsum(acc[v]);
        if (lane == 0) {
            if (v == 0) bias = __ldg(&bih[row]) + __ldg(&bhh[row]);
            g_table[(size_t)which * V * G4 + (size_t)v * G4 + row] = s + bias;
        }
    }
}

// ---------------------------------------------------------------------------
// Persistent LSTM kernel. 148 CTAs x 1024 threads.
// Weights: int16; 49 of 56 rows live in SMEM (reloaded per phase), 7 rows
// stream from L2. Work layout: 32 warps = 8 row-groups x 4 k-slices; each
// warp caches its 512-float h-slice in registers and reuses it across its
// 7 rows, reducing h shared-memory traffic 7x.
// local row lr = h_local*4 + gate;  global row = gate*H + j0 + h_local.
// ---------------------------------------------------------------------------
__global__ __launch_bounds__(1024, 1) void k_main(
    const int*   __restrict__ x,      const int*   __restrict__ target,
    const float* __restrict__ eps,
    const float* __restrict__ mu_W,    const float* __restrict__ mu_b,
    const float* __restrict__ lv_W,    const float* __restrict__ lv_b,
    float* __restrict__ out)
{
    extern __shared__ __align__(16) unsigned s_dyn[];
    unsigned* s_w     = s_dyn + OFF_W;           // [49][1024] u32 (2 shorts each)
    float*    s_h     = (float*)(s_dyn + OFF_H); // [2048]
    float*    s_part  = (float*)(s_dyn + OFF_PART);  // [56][4]
    float*    s_gates = (float*)(s_dyn + OFF_GATES); // [56]
    float*    s_c     = (float*)(s_dyn + OFF_C);     // [14]

    const int tid = threadIdx.x, lane = tid & 31, w = tid >> 5;
    const int g = w >> 2;        // row-group 0..7
    const int q = w & 3;         // k-slice 0..3
    const int j0 = blockIdx.x * CPB;
    int nloc = H - j0;
    if (nloc > CPB) nloc = CPB;
    if (nloc < 0)  nloc = 0;
    const int nrows = nloc * 4;

    if (tid < CPB) s_c[tid] = 0.0f;

    int rb = 0;  // read-buffer parity for g_h

    for (int phase = 0; phase < 2; phase++) {
        const short* Wq    = g_Wq[phase];
        const float* wsc   = g_wscale[phase];
        const float* table = g_table + (size_t)phase * V * G4;

        // ---- load SMEM-resident weight rows for this phase ----
        __syncthreads();   // everyone done with previous phase's s_w
        {
            const unsigned* Wq32 = reinterpret_cast<const unsigned*>(Wq);
            int lim = nrows < SMEM_ROWS ? nrows : SMEM_ROWS;
            for (int lr = 0; lr < lim; lr++) {
                const int row = (lr & 3) * H + j0 + (lr >> 2);
                s_w[lr * 1024 + tid] = __ldg(&Wq32[(size_t)row * 1024 + tid]);
            }
        }
        __syncthreads();

        for (int t = 0; t < T; t++) {
            // broadcast full h into smem (L2-coherent loads)
            for (int j = tid; j < H; j += 1024) s_h[j] = __ldcg(&g_h[rb][j]);
            __syncthreads();

            const int tok = (phase == 0) ? __ldg(&x[t])
                                         : (t == 0 ? 0 : __ldg(&target[t - 1]));

            // per-warp h-slice in registers: k = q*512 + c*128 + lane*4
            const float4* sh4 = reinterpret_cast<const float4*>(s_h);
            float4 hv[4];
#pragma unroll
            for (int c = 0; c < 4; c++)
                hv[c] = sh4[q * 128 + c * 32 + lane];

            const int lr0 = g * 7;
            if (g < 7) {
                // SMEM weights
                const uint2* wr = reinterpret_cast<const uint2*>(s_w) +
                                  (size_t)lr0 * 512 + q * 128 + lane;
#pragma unroll
                for (int r = 0; r < 7; r++) {
                    const int lr = lr0 + r;
                    if (lr < nrows) {
                        float acc = 0.0f;
#pragma unroll
                        for (int c = 0; c < 4; c++) {
                            uint2 ab = wr[(size_t)r * 512 + c * 32];
                            short2 p0 = *reinterpret_cast<short2*>(&ab.x);
                            short2 p1 = *reinterpret_cast<short2*>(&ab.y);
                            acc += (float)p0.x * hv[c].x + (float)p0.y * hv[c].y;
                            acc += (float)p1.x * hv[c].z + (float)p1.y * hv[c].w;
                        }
                        acc = warpsum(acc);
                        if (lane == 0) s_part[lr * 4 + q] = acc;
                    }
                }
            } else {
                // L2-streamed weights (rows 49..55)
#pragma unroll
                for (int r = 0; r < 7; r++) {
                    const int lr = lr0 + r;
                    if (lr < nrows) {
                        const int row = (lr & 3) * H + j0 + (lr >> 2);
                        const uint2* gw = reinterpret_cast<const uint2*>(
                            Wq + (size_t)row * H) + q * 128 + lane;
                        float acc = 0.0f;
#pragma unroll
                        for (int c = 0; c < 4; c++) {
                            uint2 ab = __ldg(&gw[c * 32]);
                            short2 p0 = *reinterpret_cast<short2*>(&ab.x);
                            short2 p1 = *reinterpret_cast<short2*>(&ab.y);
                            acc += (float)p0.x * hv[c].x + (float)p0.y * hv[c].y;
                            acc += (float)p1.x * hv[c].z + (float)p1.y * hv[c].w;
                        }
                        acc = warpsum(acc);
                        if (lane == 0) s_part[lr * 4 + q] = acc;
                    }
                }
            }
            __syncthreads();

            // combine 4 slice-partials, dequant, add table
            if (tid < nrows) {
                const int row = (tid & 3) * H + j0 + (tid >> 2);
                float s = s_part[tid * 4 + 0] + s_part[tid * 4 + 1] +
                          s_part[tid * 4 + 2] + s_part[tid * 4 + 3];
                s_gates[tid] = s * __ldg(&wsc[row]) +
                               __ldg(&table[(size_t)tok * G4 + row]);
            }
            __syncthreads();

            if (tid < nloc) {
                const float gi = s_gates[tid * 4 + 0];
                const float gf = s_gates[tid * 4 + 1];
                const float gg = s_gates[tid * 4 + 2];
                const float go = s_gates[tid * 4 + 3];
                float c = sigm(gf) * s_c[tid] + sigm(gi) * tanhf(gg);
                s_c[tid] = c;
                float h = sigm(go) * tanhf(c);
                __stcg(&g_h[rb ^ 1][j0 + tid], h);
                if (phase)  // dec_outs
                    out[512 + (size_t)t * H + j0 + tid] = h;
            }
            __threadfence();
            grid_sync();
            rb ^= 1;
        }

        if (phase == 0) {
            // VAE heads: mu, logvar from h_enc (in g_h[rb]); z -> g_h[rb^1]
            for (int j = tid; j < H; j += 1024) s_h[j] = __ldcg(&g_h[rb][j]);
            __syncthreads();
            const float4* sh4 = reinterpret_cast<const float4*>(s_h);
            if (w < nloc * 2) {
                const int l = w >> 1, m = w & 1;
                const float* Wm = m ? lv_W : mu_W;
                const int row = j0 + l;
                const float4* W4 = reinterpret_cast<const float4*>(Wm) + (size_t)row * (H / 4);
                float s = 0.0f;
#pragma unroll 8
                for (int i = lane; i < H / 4; i += 32) {
                    float4 a = __ldg(&W4[i]);
                    float4 b = sh4[i];
                    s += a.x * b.x + a.y * b.y + a.z * b.z + a.w * b.w;
                }
                s = warpsum(s);
                if (lane == 0)
                    s_gates[w] = s + __ldg(&(m ? lv_b : mu_b)[row]);
            }
            __syncthreads();
            if (tid < nloc) {
                const int j = j0 + tid;
                const float mu = s_gates[tid * 2 + 0];
                const float lv = s_gates[tid * 2 + 1];
                out[512 + (size_t)T * H + j]     = mu;
                out[512 + (size_t)T * H + H + j] = lv;
                float z = mu + __ldg(&eps[j]) * expf(0.5f * lv);
                __stcg(&g_h[rb ^ 1][j], z);
            }
            __threadfence();
            grid_sync();
            rb ^= 1;
        }
    }
}

// ---------------------------------------------------------------------------
// Argmax over hidden dim of each decoder output row (first-index tie-break).
// ---------------------------------------------------------------------------
__global__ __launch_bounds__(256) void k_argmax(float* __restrict__ out)
{
    __shared__ float sv[256];
    __shared__ int   si[256];
    const int t = blockIdx.x;
    const float* row = out + 512 + (size_t)t * H;
    float best = -3.402823466e+38f;
    int   bi = 0;
    for (int j = threadIdx.x; j < H; j += 256) {
        float v = row[j];
        if (v > best) { best = v; bi = j; }
    }
    sv[threadIdx.x] = best;
    si[threadIdx.x] = bi;
    __syncthreads();
    for (int s = 128; s; s >>= 1) {
        if (threadIdx.x < s) {
            float ov = sv[threadIdx.x + s];
            int   oi = si[threadIdx.x + s];
            if (ov > sv[threadIdx.x] ||
                (ov == sv[threadIdx.x] && oi < si[threadIdx.x])) {
                sv[threadIdx.x] = ov;
                si[threadIdx.x] = oi;
            }
        }
        __syncthreads();
    }
    if (threadIdx.x == 0) out[t] = (float)si[0];
}

// ---------------------------------------------------------------------------
extern "C" void kernel_launch(void* const* d_in, const int* in_sizes, int n_in,
                              void* d_out, int out_size)
{
    const int*   x       = (const int*)  d_in[0];
    const int*   target  = (const int*)  d_in[1];
    const float* eps     = (const float*)d_in[2];
    const float* enc_emb = (const float*)d_in[3];
    const float* enc_Wih = (const float*)d_in[4];
    const float* enc_Whh = (const float*)d_in[5];
    const float* enc_bih = (const float*)d_in[6];
    const float* enc_bhh = (const float*)d_in[7];
    const float* mu_W    = (const float*)d_in[8];
    const float* mu_b    = (const float*)d_in[9];
    const float* lv_W    = (const float*)d_in[10];
    const float* lv_b    = (const float*)d_in[11];
    const float* dec_emb = (const float*)d_in[12];
    const float* dec_Wih = (const float*)d_in[13];
    const float* dec_Whh = (const float*)d_in[14];
    const float* dec_bih = (const float*)d_in[15];
    const float* dec_bhh = (const float*)d_in[16];
    float* out = (float*)d_out;

    cudaFuncSetAttribute(k_main, cudaFuncAttributeMaxDynamicSharedMemorySize,
                         SMEM_BYTES);

    k_pre<<<2048, 256>>>(enc_emb, enc_Wih, enc_bih, enc_bhh,
                         dec_emb, dec_Wih, dec_bih, dec_bhh);
    k_quant<<<2 * G4, 256>>>(enc_Whh, dec_Whh);
    k_main<<<NCTA, 1024, SMEM_BYTES>>>(x, target, eps,
                                       mu_W, mu_b, lv_W, lv_b, out);
    k_argmax<<<512, 256>>>(out);
}